// round 3
// baseline (speedup 1.0000x reference)
#include <cuda_runtime.h>
#include <cstdint>

#define NN    40000
#define DH    128
#define DOUT  64
#define EMAX  700000

// ---------------- scratch (device globals; no allocation allowed) ----------------
__device__ __align__(16) float g_dinv[NN];
__device__ __align__(16) float g_hs1 [NN * DH];    // dinv-prescaled h1 = dinv * (x@W1)
__device__ __align__(16) float g_h1r [NN * DH];    // relu(layer1 output)
__device__ __align__(16) float g_hs2 [NN * DOUT];  // dinv-prescaled h2
__device__ int g_cnt [NN];                          // in-degree (excl self)
__device__ int g_off [NN + 1];                      // CSR row offsets
__device__ int g_fill[NN];                          // CSR fill cursors
__device__ int g_csr_src[EMAX];                     // CSR column (src) indices
__device__ int g_is64;                              // edge_index element width flag

struct f4acc { float x, y, z, w; };
__device__ __forceinline__ void acc4(f4acc& a, float4 v) {
    a.x += v.x; a.y += v.y; a.z += v.z; a.w += v.w;
}
struct f2acc { float x, y; };
__device__ __forceinline__ void acc2(f2acc& a, float2 v) { a.x += v.x; a.y += v.y; }

// ---------------- edge-index width detection ----------------
// int64 values < 40000: every odd 32-bit word is a zero high-half.
__global__ void k_detect(const int* __restrict__ ei32) {
    if (threadIdx.x == 0) {
        int zeros = 0;
        #pragma unroll
        for (int i = 1; i < 128; i += 2) zeros += (ei32[i] == 0);
        g_is64 = (zeros >= 48) ? 1 : 0;
    }
}

__device__ __forceinline__ void load_edge(const void* ei, int e, int E, int& s, int& d) {
    if (g_is64) {
        const long long* p = (const long long*)ei;
        s = (int)p[e]; d = (int)p[E + e];
    } else {
        const int* p = (const int*)ei;
        s = p[e]; d = p[E + e];
    }
}

// ---------------- CSR build ----------------
__global__ void k_zero() {
    int i = blockIdx.x * blockDim.x + threadIdx.x;
    if (i < NN) g_cnt[i] = 0;
}

__global__ void k_count(const void* __restrict__ ei, int E) {
    int e = blockIdx.x * blockDim.x + threadIdx.x;
    if (e < E) {
        int s, d; load_edge(ei, e, E, s, d);
        if ((unsigned)d < NN) atomicAdd(&g_cnt[d], 1);
    }
}

// single-block scan: offsets, fill cursors, dinv = rsqrt(deg+1)
#define SCAN_T 1024
#define SCAN_CH 40               // 1024*40 = 40960 >= NN
__global__ void k_scan() {
    __shared__ int ssum[SCAN_T];
    int t  = threadIdx.x;
    int lo = t * SCAN_CH;
    int hi = min(lo + SCAN_CH, NN);
    int s = 0;
    for (int i = lo; i < hi; i++) s += g_cnt[i];
    ssum[t] = s;
    __syncthreads();
    for (int d = 1; d < SCAN_T; d <<= 1) {
        int v = (t >= d) ? ssum[t - d] : 0;
        __syncthreads();
        ssum[t] += v;
        __syncthreads();
    }
    int run = ssum[t] - s;       // exclusive prefix
    for (int i = lo; i < hi; i++) {
        int c = g_cnt[i];
        g_off[i]  = run;
        g_fill[i] = run;
        g_dinv[i] = rsqrtf((float)c + 1.0f);
        run += c;
    }
    if (lo < NN && hi == NN) g_off[NN] = run;
}

__global__ void k_fill(const void* __restrict__ ei, int E) {
    int e = blockIdx.x * blockDim.x + threadIdx.x;
    if (e < E) {
        int s, d; load_edge(ei, e, E, s, d);
        if ((unsigned)s < NN && (unsigned)d < NN) {
            int pos = atomicAdd(&g_fill[d], 1);
            if (pos < EMAX) g_csr_src[pos] = s;
        }
    }
}

// ---------------- fused GEMM + dinv prescale ----------------
// X: [M,128] row-major, W: [128,N]. Tile: 64 rows/block.
template<int N, int LAYER>
__global__ void k_gemm_scale(const float* __restrict__ Xin, const float* __restrict__ W) {
    constexpr int K    = 128;
    constexpr int CPT  = 4;
    constexpr int CT   = N / CPT;     // 32 (N=128) or 16 (N=64)
    constexpr int RPT  = 8;
    constexpr int RT   = 8;
    constexpr int ROWS = RT * RPT;    // 64
    __shared__ float sX[ROWS * K];    // 32 KB

    const float* X  = (LAYER == 1) ? Xin : g_h1r;
    float*       hs = (LAYER == 1) ? g_hs1 : g_hs2;

    const int tid      = threadIdx.x;
    const int nthreads = CT * RT;
    const int row0     = blockIdx.x * ROWS;

    const float4* xg = (const float4*)(X + (size_t)row0 * K);
    for (int idx = tid; idx < ROWS * K / 4; idx += nthreads)
        ((float4*)sX)[idx] = xg[idx];
    __syncthreads();

    const int c     = (tid % CT) * CPT;
    const int rbase = (tid / CT) * RPT;

    float acc[RPT][CPT];
    #pragma unroll
    for (int i = 0; i < RPT; i++)
        #pragma unroll
        for (int j = 0; j < CPT; j++) acc[i][j] = 0.0f;

    #pragma unroll 4
    for (int k = 0; k < K; k++) {
        float4 w = *(const float4*)(W + k * N + c);
        #pragma unroll
        for (int i = 0; i < RPT; i++) {
            float xv = sX[(rbase + i) * K + k];
            acc[i][0] += xv * w.x;
            acc[i][1] += xv * w.y;
            acc[i][2] += xv * w.z;
            acc[i][3] += xv * w.w;
        }
    }

    #pragma unroll
    for (int i = 0; i < RPT; i++) {
        int   r = row0 + rbase + i;
        float d = g_dinv[r];
        *(float4*)(hs + (size_t)r * N + c) =
            make_float4(acc[i][0]*d, acc[i][1]*d, acc[i][2]*d, acc[i][3]*d);
    }
}

// ---------------- pull aggregation: one warp per destination node ----------------
// out[i] = relu_or_id( dinv[i] * (hs[i] + sum_{s in nbr(i)} hs[s]) + b )
__global__ void k_aggr1(const float* __restrict__ b1) {
    int node = blockIdx.x * 8 + (threadIdx.x >> 5);
    if (node >= NN) return;
    int lane = threadIdx.x & 31;
    const float4* hs = (const float4*)g_hs1;   // 32 float4 per node

    f4acc a0, a1, a2, a3;
    float4 self = hs[node * 32 + lane];
    a0.x = self.x; a0.y = self.y; a0.z = self.z; a0.w = self.w;
    a1 = {0,0,0,0}; a2 = {0,0,0,0}; a3 = {0,0,0,0};

    int off0 = g_off[node], off1 = g_off[node + 1];
    for (int base = off0; base < off1; base += 32) {
        int idx = base + lane;
        int s   = (idx < off1) ? __ldg(&g_csr_src[idx]) : 0;
        int m   = min(32, off1 - base);
        int k   = 0;
        for (; k + 4 <= m; k += 4) {
            int s0 = __shfl_sync(0xffffffffu, s, k);
            int s1 = __shfl_sync(0xffffffffu, s, k + 1);
            int s2 = __shfl_sync(0xffffffffu, s, k + 2);
            int s3 = __shfl_sync(0xffffffffu, s, k + 3);
            float4 v0 = hs[s0 * 32 + lane];
            float4 v1 = hs[s1 * 32 + lane];
            float4 v2 = hs[s2 * 32 + lane];
            float4 v3 = hs[s3 * 32 + lane];
            acc4(a0, v0); acc4(a1, v1); acc4(a2, v2); acc4(a3, v3);
        }
        for (; k < m; k++) {
            int sk = __shfl_sync(0xffffffffu, s, k);
            acc4(a0, hs[sk * 32 + lane]);
        }
    }
    float d   = g_dinv[node];
    float4 bb = ((const float4*)b1)[lane];
    float4 r;
    r.x = fmaxf(0.0f, (a0.x + a1.x + a2.x + a3.x) * d + bb.x);
    r.y = fmaxf(0.0f, (a0.y + a1.y + a2.y + a3.y) * d + bb.y);
    r.z = fmaxf(0.0f, (a0.z + a1.z + a2.z + a3.z) * d + bb.z);
    r.w = fmaxf(0.0f, (a0.w + a1.w + a2.w + a3.w) * d + bb.w);
    ((float4*)g_h1r)[node * 32 + lane] = r;
}

__global__ void k_aggr2(const float* __restrict__ b2, float* __restrict__ out) {
    int node = blockIdx.x * 8 + (threadIdx.x >> 5);
    if (node >= NN) return;
    int lane = threadIdx.x & 31;
    const float2* hs = (const float2*)g_hs2;   // 32 float2 per node

    f2acc a0, a1, a2, a3;
    float2 self = hs[node * 32 + lane];
    a0.x = self.x; a0.y = self.y;
    a1 = {0,0}; a2 = {0,0}; a3 = {0,0};

    int off0 = g_off[node], off1 = g_off[node + 1];
    for (int base = off0; base < off1; base += 32) {
        int idx = base + lane;
        int s   = (idx < off1) ? __ldg(&g_csr_src[idx]) : 0;
        int m   = min(32, off1 - base);
        int k   = 0;
        for (; k + 4 <= m; k += 4) {
            int s0 = __shfl_sync(0xffffffffu, s, k);
            int s1 = __shfl_sync(0xffffffffu, s, k + 1);
            int s2 = __shfl_sync(0xffffffffu, s, k + 2);
            int s3 = __shfl_sync(0xffffffffu, s, k + 3);
            float2 v0 = hs[s0 * 32 + lane];
            float2 v1 = hs[s1 * 32 + lane];
            float2 v2 = hs[s2 * 32 + lane];
            float2 v3 = hs[s3 * 32 + lane];
            acc2(a0, v0); acc2(a1, v1); acc2(a2, v2); acc2(a3, v3);
        }
        for (; k < m; k++) {
            int sk = __shfl_sync(0xffffffffu, s, k);
            acc2(a0, hs[sk * 32 + lane]);
        }
    }
    float d   = g_dinv[node];
    float2 bb = ((const float2*)b2)[lane];
    float2 r;
    r.x = (a0.x + a1.x + a2.x + a3.x) * d + bb.x;
    r.y = (a0.y + a1.y + a2.y + a3.y) * d + bb.y;
    ((float2*)out)[node * 32 + lane] = r;
}

// ---------------- launch ----------------
extern "C" void kernel_launch(void* const* d_in, const int* in_sizes, int n_in,
                              void* d_out, int out_size) {
    const float* x  = (const float*)d_in[0];
    const void*  ei = d_in[1];
    const float* W1 = (const float*)d_in[2];
    const float* b1 = (const float*)d_in[3];
    const float* W2 = (const float*)d_in[4];
    const float* b2 = (const float*)d_in[5];
    const int E = in_sizes[1] / 2;          // element count identical under int32/int64 views

    k_detect<<<1, 32>>>((const int*)ei);
    k_zero  <<<(NN + 255) / 256, 256>>>();
    k_count <<<(E + 255) / 256, 256>>>(ei, E);
    k_scan  <<<1, SCAN_T>>>();
    k_fill  <<<(E + 255) / 256, 256>>>(ei, E);

    // Layer 1
    k_gemm_scale<DH, 1><<<NN / 64, 32 * 8>>>(x, W1);
    k_aggr1<<<(NN + 7) / 8, 256>>>(b1);

    // Layer 2
    k_gemm_scale<DOUT, 2><<<NN / 64, 16 * 8>>>(nullptr, W2);
    k_aggr2<<<(NN + 7) / 8, 256>>>(b2, (float*)d_out);
}

// round 4
// speedup vs baseline: 2.0444x; 2.0444x over previous
#include <cuda_runtime.h>
#include <cstdint>

#define NN    40000
#define DH    128
#define DOUT  64
#define EMAX  700000
#define NB    157           // ceil(40000/256)

// ---------------- scratch (device globals; no allocation allowed) ----------------
__device__ __align__(16) float g_dinv[NN];
__device__ __align__(16) float g_hs1 [NN * DH];    // dinv-prescaled h1 = dinv * (x@W1)
__device__ __align__(16) float g_h1r [NN * DH];    // relu(layer1 output)
__device__ __align__(16) float g_hs2 [NN * DOUT];  // dinv-prescaled h2
__device__ int g_cnt [NN];                          // in-degree (excl self)
__device__ int g_off [NN + 1];                      // CSR row offsets
__device__ int g_fill[NN];                          // CSR fill cursors
__device__ int g_csr_src[EMAX];                     // CSR column (src) indices
__device__ int g_bsum[NB];                          // per-block count sums
__device__ int g_boff[NB];                          // per-block exclusive offsets
__device__ int g_is64;                              // edge_index element width flag

struct f4acc { float x, y, z, w; };
__device__ __forceinline__ void acc4(f4acc& a, float4 v) {
    a.x += v.x; a.y += v.y; a.z += v.z; a.w += v.w;
}
struct f2acc { float x, y; };
__device__ __forceinline__ void acc2(f2acc& a, float2 v) { a.x += v.x; a.y += v.y; }

// ---------------- detect edge width + zero counts (fused) ----------------
__global__ void k_init(const int* __restrict__ ei32) {
    int i = blockIdx.x * blockDim.x + threadIdx.x;
    if (i < NN) g_cnt[i] = 0;
    if (blockIdx.x == 0 && threadIdx.x == 0) {
        int zeros = 0;
        #pragma unroll
        for (int j = 1; j < 128; j += 2) zeros += (ei32[j] == 0);
        g_is64 = (zeros >= 48) ? 1 : 0;
    }
}

__device__ __forceinline__ void load_edge(const void* ei, int e, int E, int& s, int& d) {
    if (g_is64) {
        const long long* p = (const long long*)ei;
        s = (int)p[e]; d = (int)p[E + e];
    } else {
        const int* p = (const int*)ei;
        s = p[e]; d = p[E + e];
    }
}

__global__ void k_count(const void* __restrict__ ei, int E) {
    int e = blockIdx.x * blockDim.x + threadIdx.x;
    if (e < E) {
        int s, d; load_edge(ei, e, E, s, d);
        if ((unsigned)d < NN) atomicAdd(&g_cnt[d], 1);
    }
}

// ---------------- chip-wide 3-phase exclusive scan ----------------
__global__ void k_bsum() {
    int i = blockIdx.x * 256 + threadIdx.x;
    int c = (i < NN) ? g_cnt[i] : 0;
    #pragma unroll
    for (int o = 16; o; o >>= 1) c += __shfl_down_sync(0xffffffffu, c, o);
    __shared__ int ws[8];
    if ((threadIdx.x & 31) == 0) ws[threadIdx.x >> 5] = c;
    __syncthreads();
    if (threadIdx.x < 8) {
        int v = ws[threadIdx.x];
        #pragma unroll
        for (int o = 4; o; o >>= 1) v += __shfl_down_sync(0xffu, v, o);
        if (threadIdx.x == 0) g_bsum[blockIdx.x] = v;
    }
}

__global__ void k_bscan() {
    __shared__ int sh[256];
    int t = threadIdx.x;
    int v = (t < NB) ? g_bsum[t] : 0;
    sh[t] = v;
    __syncthreads();
    for (int d = 1; d < 256; d <<= 1) {
        int u = (t >= d) ? sh[t - d] : 0;
        __syncthreads();
        sh[t] += u;
        __syncthreads();
    }
    if (t < NB) g_boff[t] = sh[t] - v;      // exclusive
    if (t == NB - 1) g_off[NN] = sh[t];     // total edge count kept
}

__global__ void k_offsets() {
    int i    = blockIdx.x * 256 + threadIdx.x;
    int c    = (i < NN) ? g_cnt[i] : 0;
    int lane = threadIdx.x & 31, w = threadIdx.x >> 5;
    int inc  = c;
    #pragma unroll
    for (int o = 1; o < 32; o <<= 1) {
        int u = __shfl_up_sync(0xffffffffu, inc, o);
        if (lane >= o) inc += u;
    }
    __shared__ int ws[8];
    if (lane == 31) ws[w] = inc;
    __syncthreads();
    if (threadIdx.x == 0) {
        int r = 0;
        #pragma unroll
        for (int j = 0; j < 8; j++) { int t = ws[j]; ws[j] = r; r += t; }
    }
    __syncthreads();
    int excl = inc - c + ws[w] + g_boff[blockIdx.x];
    if (i < NN) {
        g_off[i]  = excl;
        g_fill[i] = excl;
        g_dinv[i] = rsqrtf((float)c + 1.0f);
    }
}

__global__ void k_fill(const void* __restrict__ ei, int E) {
    int e = blockIdx.x * blockDim.x + threadIdx.x;
    if (e < E) {
        int s, d; load_edge(ei, e, E, s, d);
        if ((unsigned)s < NN && (unsigned)d < NN) {
            int pos = atomicAdd(&g_fill[d], 1);
            if (pos < EMAX) g_csr_src[pos] = s;
        }
    }
}

// ---------------- fused GEMM + dinv prescale ----------------
// X: [M,128] row-major, W: [128,N]. Tile: 64 rows/block.
template<int N, int LAYER>
__global__ void k_gemm_scale(const float* __restrict__ Xin, const float* __restrict__ W) {
    constexpr int K    = 128;
    constexpr int CPT  = 4;
    constexpr int CT   = N / CPT;     // 32 (N=128) or 16 (N=64)
    constexpr int RPT  = 8;
    constexpr int RT   = 8;
    constexpr int ROWS = RT * RPT;    // 64
    __shared__ float sX[ROWS * K];    // 32 KB

    const float* X  = (LAYER == 1) ? Xin : g_h1r;
    float*       hs = (LAYER == 1) ? g_hs1 : g_hs2;

    const int tid      = threadIdx.x;
    const int nthreads = CT * RT;
    const int row0     = blockIdx.x * ROWS;

    const float4* xg = (const float4*)(X + (size_t)row0 * K);
    for (int idx = tid; idx < ROWS * K / 4; idx += nthreads)
        ((float4*)sX)[idx] = xg[idx];
    __syncthreads();

    const int c     = (tid % CT) * CPT;
    const int rbase = (tid / CT) * RPT;

    float acc[RPT][CPT];
    #pragma unroll
    for (int i = 0; i < RPT; i++)
        #pragma unroll
        for (int j = 0; j < CPT; j++) acc[i][j] = 0.0f;

    #pragma unroll 4
    for (int k = 0; k < K; k++) {
        float4 w = *(const float4*)(W + k * N + c);
        #pragma unroll
        for (int i = 0; i < RPT; i++) {
            float xv = sX[(rbase + i) * K + k];
            acc[i][0] += xv * w.x;
            acc[i][1] += xv * w.y;
            acc[i][2] += xv * w.z;
            acc[i][3] += xv * w.w;
        }
    }

    #pragma unroll
    for (int i = 0; i < RPT; i++) {
        int   r = row0 + rbase + i;
        float d = g_dinv[r];
        *(float4*)(hs + (size_t)r * N + c) =
            make_float4(acc[i][0]*d, acc[i][1]*d, acc[i][2]*d, acc[i][3]*d);
    }
}

// ---------------- pull aggregation: one warp per destination node ----------------
__global__ void k_aggr1(const float* __restrict__ b1) {
    int node = blockIdx.x * 8 + (threadIdx.x >> 5);
    if (node >= NN) return;
    int lane = threadIdx.x & 31;
    const float4* hs = (const float4*)g_hs1;   // 32 float4 per node

    f4acc a0, a1, a2, a3;
    float4 self = hs[node * 32 + lane];
    a0.x = self.x; a0.y = self.y; a0.z = self.z; a0.w = self.w;
    a1 = {0,0,0,0}; a2 = {0,0,0,0}; a3 = {0,0,0,0};

    int off0 = g_off[node], off1 = g_off[node + 1];
    for (int base = off0; base < off1; base += 32) {
        int idx = base + lane;
        int s   = (idx < off1) ? __ldg(&g_csr_src[idx]) : 0;
        int m   = min(32, off1 - base);
        int k   = 0;
        for (; k + 4 <= m; k += 4) {
            int s0 = __shfl_sync(0xffffffffu, s, k);
            int s1 = __shfl_sync(0xffffffffu, s, k + 1);
            int s2 = __shfl_sync(0xffffffffu, s, k + 2);
            int s3 = __shfl_sync(0xffffffffu, s, k + 3);
            float4 v0 = hs[s0 * 32 + lane];
            float4 v1 = hs[s1 * 32 + lane];
            float4 v2 = hs[s2 * 32 + lane];
            float4 v3 = hs[s3 * 32 + lane];
            acc4(a0, v0); acc4(a1, v1); acc4(a2, v2); acc4(a3, v3);
        }
        for (; k < m; k++) {
            int sk = __shfl_sync(0xffffffffu, s, k);
            acc4(a0, hs[sk * 32 + lane]);
        }
    }
    float d   = g_dinv[node];
    float4 bb = ((const float4*)b1)[lane];
    float4 r;
    r.x = fmaxf(0.0f, (a0.x + a1.x + a2.x + a3.x) * d + bb.x);
    r.y = fmaxf(0.0f, (a0.y + a1.y + a2.y + a3.y) * d + bb.y);
    r.z = fmaxf(0.0f, (a0.z + a1.z + a2.z + a3.z) * d + bb.z);
    r.w = fmaxf(0.0f, (a0.w + a1.w + a2.w + a3.w) * d + bb.w);
    ((float4*)g_h1r)[node * 32 + lane] = r;
}

__global__ void k_aggr2(const float* __restrict__ b2, float* __restrict__ out) {
    int node = blockIdx.x * 8 + (threadIdx.x >> 5);
    if (node >= NN) return;
    int lane = threadIdx.x & 31;
    const float2* hs = (const float2*)g_hs2;   // 32 float2 per node

    f2acc a0, a1, a2, a3;
    float2 self = hs[node * 32 + lane];
    a0.x = self.x; a0.y = self.y;
    a1 = {0,0}; a2 = {0,0}; a3 = {0,0};

    int off0 = g_off[node], off1 = g_off[node + 1];
    for (int base = off0; base < off1; base += 32) {
        int idx = base + lane;
        int s   = (idx < off1) ? __ldg(&g_csr_src[idx]) : 0;
        int m   = min(32, off1 - base);
        int k   = 0;
        for (; k + 4 <= m; k += 4) {
            int s0 = __shfl_sync(0xffffffffu, s, k);
            int s1 = __shfl_sync(0xffffffffu, s, k + 1);
            int s2 = __shfl_sync(0xffffffffu, s, k + 2);
            int s3 = __shfl_sync(0xffffffffu, s, k + 3);
            float2 v0 = hs[s0 * 32 + lane];
            float2 v1 = hs[s1 * 32 + lane];
            float2 v2 = hs[s2 * 32 + lane];
            float2 v3 = hs[s3 * 32 + lane];
            acc2(a0, v0); acc2(a1, v1); acc2(a2, v2); acc2(a3, v3);
        }
        for (; k < m; k++) {
            int sk = __shfl_sync(0xffffffffu, s, k);
            acc2(a0, hs[sk * 32 + lane]);
        }
    }
    float d   = g_dinv[node];
    float2 bb = ((const float2*)b2)[lane];
    float2 r;
    r.x = (a0.x + a1.x + a2.x + a3.x) * d + bb.x;
    r.y = (a0.y + a1.y + a2.y + a3.y) * d + bb.y;
    ((float2*)out)[node * 32 + lane] = r;
}

// ---------------- launch ----------------
extern "C" void kernel_launch(void* const* d_in, const int* in_sizes, int n_in,
                              void* d_out, int out_size) {
    const float* x  = (const float*)d_in[0];
    const void*  ei = d_in[1];
    const float* W1 = (const float*)d_in[2];
    const float* b1 = (const float*)d_in[3];
    const float* W2 = (const float*)d_in[4];
    const float* b2 = (const float*)d_in[5];
    const int E = in_sizes[1] / 2;

    k_init   <<<NB, 256>>>((const int*)ei);
    k_count  <<<(E + 255) / 256, 256>>>(ei, E);
    k_bsum   <<<NB, 256>>>();
    k_bscan  <<<1, 256>>>();
    k_offsets<<<NB, 256>>>();
    k_fill   <<<(E + 255) / 256, 256>>>(ei, E);

    // Layer 1
    k_gemm_scale<DH, 1><<<NN / 64, 32 * 8>>>(x, W1);
    k_aggr1<<<(NN + 7) / 8, 256>>>(b1);

    // Layer 2
    k_gemm_scale<DOUT, 2><<<NN / 64, 16 * 8>>>(nullptr, W2);
    k_aggr2<<<(NN + 7) / 8, 256>>>(b2, (float*)d_out);
}

// round 5
// speedup vs baseline: 3.0736x; 1.5034x over previous
#include <cuda_runtime.h>
#include <cstdint>

#define NN    40000
#define DH    128
#define DOUT  64
#define EMAX  700000
#define NB    157           // ceil(40000/256)

// ---------------- scratch (device globals; no allocation allowed) ----------------
__device__ __align__(16) float g_dinv[NN];
__device__ __align__(16) float g_hs1 [NN * DH];    // dinv-prescaled h1 = dinv * (x@W1)
__device__ __align__(16) float g_h1r [NN * DH];    // relu(layer1 output)
__device__ __align__(16) float g_hs2 [NN * DOUT];  // dinv-prescaled h2
__device__ int g_cnt [NN];
__device__ int g_off [NN + 1];
__device__ int g_fill[NN];
__device__ int g_csr_src[EMAX];
__device__ int g_bsum[NB];
__device__ int g_boff[NB];
__device__ int g_is64;

struct f4acc { float x, y, z, w; };
__device__ __forceinline__ void acc4(f4acc& a, float4 v) {
    a.x += v.x; a.y += v.y; a.z += v.z; a.w += v.w;
}
struct f2acc { float x, y; };
__device__ __forceinline__ void acc2(f2acc& a, float2 v) { a.x += v.x; a.y += v.y; }

__device__ __forceinline__ uint32_t f2tf32(float f) {
    uint32_t u; asm("cvt.rna.tf32.f32 %0, %1;" : "=r"(u) : "f"(f)); return u;
}
__device__ __forceinline__ void mma_tf32(float4& c, uint32_t a0, uint32_t a1,
                                         uint32_t a2, uint32_t a3,
                                         uint32_t b0, uint32_t b1) {
    asm volatile("mma.sync.aligned.m16n8k8.row.col.f32.tf32.tf32.f32 "
                 "{%0,%1,%2,%3}, {%4,%5,%6,%7}, {%8,%9}, {%0,%1,%2,%3};"
                 : "+f"(c.x), "+f"(c.y), "+f"(c.z), "+f"(c.w)
                 : "r"(a0), "r"(a1), "r"(a2), "r"(a3), "r"(b0), "r"(b1));
}

// ---------------- detect edge width + zero counts (fused) ----------------
__global__ void k_init(const int* __restrict__ ei32) {
    int i = blockIdx.x * blockDim.x + threadIdx.x;
    if (i < NN) g_cnt[i] = 0;
    if (blockIdx.x == 0 && threadIdx.x == 0) {
        int zeros = 0;
        #pragma unroll
        for (int j = 1; j < 128; j += 2) zeros += (ei32[j] == 0);
        g_is64 = (zeros >= 48) ? 1 : 0;
    }
}

__device__ __forceinline__ void load_edge(const void* ei, int e, int E, int& s, int& d) {
    if (g_is64) {
        const long long* p = (const long long*)ei;
        s = (int)p[e]; d = (int)p[E + e];
    } else {
        const int* p = (const int*)ei;
        s = p[e]; d = p[E + e];
    }
}

__global__ void k_count(const void* __restrict__ ei, int E) {
    int e = blockIdx.x * blockDim.x + threadIdx.x;
    if (e < E) {
        int s, d; load_edge(ei, e, E, s, d);
        if ((unsigned)d < NN) atomicAdd(&g_cnt[d], 1);
    }
}

// ---------------- chip-wide 3-phase exclusive scan ----------------
__global__ void k_bsum() {
    int i = blockIdx.x * 256 + threadIdx.x;
    int c = (i < NN) ? g_cnt[i] : 0;
    #pragma unroll
    for (int o = 16; o; o >>= 1) c += __shfl_down_sync(0xffffffffu, c, o);
    __shared__ int ws[8];
    if ((threadIdx.x & 31) == 0) ws[threadIdx.x >> 5] = c;
    __syncthreads();
    if (threadIdx.x < 8) {
        int v = ws[threadIdx.x];
        #pragma unroll
        for (int o = 4; o; o >>= 1) v += __shfl_down_sync(0xffu, v, o);
        if (threadIdx.x == 0) g_bsum[blockIdx.x] = v;
    }
}

__global__ void k_bscan() {
    __shared__ int sh[256];
    int t = threadIdx.x;
    int v = (t < NB) ? g_bsum[t] : 0;
    sh[t] = v;
    __syncthreads();
    for (int d = 1; d < 256; d <<= 1) {
        int u = (t >= d) ? sh[t - d] : 0;
        __syncthreads();
        sh[t] += u;
        __syncthreads();
    }
    if (t < NB) g_boff[t] = sh[t] - v;
    if (t == NB - 1) g_off[NN] = sh[t];
}

__global__ void k_offsets() {
    int i    = blockIdx.x * 256 + threadIdx.x;
    int c    = (i < NN) ? g_cnt[i] : 0;
    int lane = threadIdx.x & 31, w = threadIdx.x >> 5;
    int inc  = c;
    #pragma unroll
    for (int o = 1; o < 32; o <<= 1) {
        int u = __shfl_up_sync(0xffffffffu, inc, o);
        if (lane >= o) inc += u;
    }
    __shared__ int ws[8];
    if (lane == 31) ws[w] = inc;
    __syncthreads();
    if (threadIdx.x == 0) {
        int r = 0;
        #pragma unroll
        for (int j = 0; j < 8; j++) { int t = ws[j]; ws[j] = r; r += t; }
    }
    __syncthreads();
    int excl = inc - c + ws[w] + g_boff[blockIdx.x];
    if (i < NN) {
        g_off[i]  = excl;
        g_fill[i] = excl;
        g_dinv[i] = rsqrtf((float)c + 1.0f);
    }
}

__global__ void k_fill(const void* __restrict__ ei, int E) {
    int e = blockIdx.x * blockDim.x + threadIdx.x;
    if (e < E) {
        int s, d; load_edge(ei, e, E, s, d);
        if ((unsigned)s < NN && (unsigned)d < NN) {
            int pos = atomicAdd(&g_fill[d], 1);
            if (pos < EMAX) g_csr_src[pos] = s;
        }
    }
}

// ---------------- tensor-core GEMM (tf32) + dinv prescale ----------------
// Block: 64 rows x N cols, 256 threads = 8 warps (4 row x 2 col).
// Warp tile: 16 x (N/2). Full K=128 staged in smem.
template<int N, int LAYER>
__global__ void k_gemm_tc(const float* __restrict__ Xin, const float* __restrict__ W) {
    constexpr int K    = 128;
    constexpr int ROWS = 64;
    constexpr int XS   = 132;       // sX row stride (words): banks 4*grp+tig distinct
    constexpr int WS   = N + 8;     // sW row stride: banks 8*tig+grp distinct
    constexpr int NW   = N / 2;     // warp n-extent (64 or 32)
    constexpr int NT   = NW / 8;    // n8 tiles per warp (8 or 4)
    extern __shared__ uint32_t smem[];
    uint32_t* sX = smem;                 // ROWS x XS
    uint32_t* sW = smem + ROWS * XS;     // K x WS

    const float* X  = (LAYER == 1) ? Xin : g_h1r;
    float*       hs = (LAYER == 1) ? g_hs1 : g_hs2;

    const int tid  = threadIdx.x;
    const int row0 = blockIdx.x * ROWS;

    // stage X tile (64 x 128 fp32 -> tf32)
    const float4* xg = (const float4*)(X + (size_t)row0 * K);
    #pragma unroll
    for (int j = tid; j < ROWS * K / 4; j += 256) {
        float4 v = xg[j];
        uint32_t* p = sX + (j >> 5) * XS + ((j & 31) << 2);
        p[0] = f2tf32(v.x); p[1] = f2tf32(v.y); p[2] = f2tf32(v.z); p[3] = f2tf32(v.w);
    }
    // stage W (K x N fp32 -> tf32)
    const float4* wg = (const float4*)W;
    #pragma unroll
    for (int j = tid; j < K * N / 4; j += 256) {
        float4 v = wg[j];
        uint32_t* p = sW + (j / (N / 4)) * WS + ((j % (N / 4)) << 2);
        p[0] = f2tf32(v.x); p[1] = f2tf32(v.y); p[2] = f2tf32(v.z); p[3] = f2tf32(v.w);
    }
    __syncthreads();

    const int warp = tid >> 5, lane = tid & 31;
    const int wr   = (warp & 3) * 16;       // warp row offset
    const int wn   = (warp >> 2) * NW;      // warp col offset
    const int grp  = lane >> 2, tig = lane & 3;

    float4 acc[NT];
    #pragma unroll
    for (int t = 0; t < NT; t++) acc[t] = make_float4(0.f, 0.f, 0.f, 0.f);

    #pragma unroll
    for (int k8 = 0; k8 < K / 8; k8++) {
        const uint32_t* ax = sX + (wr + grp) * XS + k8 * 8 + tig;
        uint32_t a0 = ax[0];
        uint32_t a1 = ax[8 * XS];
        uint32_t a2 = ax[4];
        uint32_t a3 = ax[8 * XS + 4];
        const uint32_t* bx = sW + (k8 * 8 + tig) * WS + wn + grp;
        #pragma unroll
        for (int t = 0; t < NT; t++) {
            uint32_t b0 = bx[t * 8];
            uint32_t b1 = bx[t * 8 + 4 * WS];
            mma_tf32(acc[t], a0, a1, a2, a3, b0, b1);
        }
    }

    // epilogue: scale by dinv(row), write float2 pairs
    const int r0 = row0 + wr + grp;
    const int r1 = r0 + 8;
    const float d0 = g_dinv[r0], d1 = g_dinv[r1];
    #pragma unroll
    for (int t = 0; t < NT; t++) {
        int c = wn + t * 8 + 2 * tig;
        *(float2*)(hs + (size_t)r0 * N + c) = make_float2(acc[t].x * d0, acc[t].y * d0);
        *(float2*)(hs + (size_t)r1 * N + c) = make_float2(acc[t].z * d1, acc[t].w * d1);
    }
}

// ---------------- pull aggregation: one warp per destination node ----------------
__global__ void k_aggr1(const float* __restrict__ b1) {
    int node = blockIdx.x * 8 + (threadIdx.x >> 5);
    if (node >= NN) return;
    int lane = threadIdx.x & 31;
    const float4* hs = (const float4*)g_hs1;

    f4acc a0, a1, a2, a3;
    float4 self = hs[node * 32 + lane];
    a0.x = self.x; a0.y = self.y; a0.z = self.z; a0.w = self.w;
    a1 = {0,0,0,0}; a2 = {0,0,0,0}; a3 = {0,0,0,0};

    int off0 = g_off[node], off1 = g_off[node + 1];
    for (int base = off0; base < off1; base += 32) {
        int idx = base + lane;
        int s   = (idx < off1) ? __ldg(&g_csr_src[idx]) : 0;
        int m   = min(32, off1 - base);
        int k   = 0;
        for (; k + 4 <= m; k += 4) {
            int s0 = __shfl_sync(0xffffffffu, s, k);
            int s1 = __shfl_sync(0xffffffffu, s, k + 1);
            int s2 = __shfl_sync(0xffffffffu, s, k + 2);
            int s3 = __shfl_sync(0xffffffffu, s, k + 3);
            float4 v0 = hs[s0 * 32 + lane];
            float4 v1 = hs[s1 * 32 + lane];
            float4 v2 = hs[s2 * 32 + lane];
            float4 v3 = hs[s3 * 32 + lane];
            acc4(a0, v0); acc4(a1, v1); acc4(a2, v2); acc4(a3, v3);
        }
        for (; k < m; k++) {
            int sk = __shfl_sync(0xffffffffu, s, k);
            acc4(a0, hs[sk * 32 + lane]);
        }
    }
    float d   = g_dinv[node];
    float4 bb = ((const float4*)b1)[lane];
    float4 r;
    r.x = fmaxf(0.0f, (a0.x + a1.x + a2.x + a3.x) * d + bb.x);
    r.y = fmaxf(0.0f, (a0.y + a1.y + a2.y + a3.y) * d + bb.y);
    r.z = fmaxf(0.0f, (a0.z + a1.z + a2.z + a3.z) * d + bb.z);
    r.w = fmaxf(0.0f, (a0.w + a1.w + a2.w + a3.w) * d + bb.w);
    ((float4*)g_h1r)[node * 32 + lane] = r;
}

__global__ void k_aggr2(const float* __restrict__ b2, float* __restrict__ out) {
    int node = blockIdx.x * 8 + (threadIdx.x >> 5);
    if (node >= NN) return;
    int lane = threadIdx.x & 31;
    const float2* hs = (const float2*)g_hs2;

    f2acc a0, a1, a2, a3;
    float2 self = hs[node * 32 + lane];
    a0.x = self.x; a0.y = self.y;
    a1 = {0,0}; a2 = {0,0}; a3 = {0,0};

    int off0 = g_off[node], off1 = g_off[node + 1];
    for (int base = off0; base < off1; base += 32) {
        int idx = base + lane;
        int s   = (idx < off1) ? __ldg(&g_csr_src[idx]) : 0;
        int m   = min(32, off1 - base);
        int k   = 0;
        for (; k + 4 <= m; k += 4) {
            int s0 = __shfl_sync(0xffffffffu, s, k);
            int s1 = __shfl_sync(0xffffffffu, s, k + 1);
            int s2 = __shfl_sync(0xffffffffu, s, k + 2);
            int s3 = __shfl_sync(0xffffffffu, s, k + 3);
            float2 v0 = hs[s0 * 32 + lane];
            float2 v1 = hs[s1 * 32 + lane];
            float2 v2 = hs[s2 * 32 + lane];
            float2 v3 = hs[s3 * 32 + lane];
            acc2(a0, v0); acc2(a1, v1); acc2(a2, v2); acc2(a3, v3);
        }
        for (; k < m; k++) {
            int sk = __shfl_sync(0xffffffffu, s, k);
            acc2(a0, hs[sk * 32 + lane]);
        }
    }
    float d   = g_dinv[node];
    float2 bb = ((const float2*)b2)[lane];
    float2 r;
    r.x = (a0.x + a1.x + a2.x + a3.x) * d + bb.x;
    r.y = (a0.y + a1.y + a2.y + a3.y) * d + bb.y;
    ((float2*)out)[node * 32 + lane] = r;
}

// ---------------- launch ----------------
extern "C" void kernel_launch(void* const* d_in, const int* in_sizes, int n_in,
                              void* d_out, int out_size) {
    const float* x  = (const float*)d_in[0];
    const void*  ei = d_in[1];
    const float* W1 = (const float*)d_in[2];
    const float* b1 = (const float*)d_in[3];
    const float* W2 = (const float*)d_in[4];
    const float* b2 = (const float*)d_in[5];
    const int E = in_sizes[1] / 2;

    constexpr int SM1 = (64 * 132 + 128 * (DH   + 8)) * 4;   // 103424 B
    constexpr int SM2 = (64 * 132 + 128 * (DOUT + 8)) * 4;   //  70656 B
    cudaFuncSetAttribute(k_gemm_tc<DH, 1>,
                         cudaFuncAttributeMaxDynamicSharedMemorySize, SM1);
    cudaFuncSetAttribute(k_gemm_tc<DOUT, 2>,
                         cudaFuncAttributeMaxDynamicSharedMemorySize, SM2);

    k_init   <<<NB, 256>>>((const int*)ei);
    k_count  <<<(E + 255) / 256, 256>>>(ei, E);
    k_bsum   <<<NB, 256>>>();
    k_bscan  <<<1, 256>>>();
    k_offsets<<<NB, 256>>>();
    k_fill   <<<(E + 255) / 256, 256>>>(ei, E);

    // Layer 1
    k_gemm_tc<DH, 1><<<NN / 64, 256, SM1>>>(x, W1);
    k_aggr1<<<(NN + 7) / 8, 256>>>(b1);

    // Layer 2
    k_gemm_tc<DOUT, 2><<<NN / 64, 256, SM2>>>(nullptr, W2);
    k_aggr2<<<(NN + 7) / 8, 256>>>(b2, (float*)d_out);
}

// round 6
// speedup vs baseline: 3.3209x; 1.0805x over previous
#include <cuda_runtime.h>
#include <cuda_fp16.h>
#include <cstdint>

#define NN    40000
#define DH    128
#define DOUT  64
#define EMAX  700000
#define NB    157           // ceil(40000/256)

// ---------------- scratch (device globals; no allocation allowed) ----------------
__device__ __align__(16) float  g_dinv[NN];
__device__ __align__(16) __half g_hs1h[NN * DH];   // fp16 dinv-prescaled h1
__device__ __align__(16) float  g_h1r [NN * DH];   // relu(layer1 out), fp32
__device__ __align__(16) __half g_hs2h[NN * DOUT]; // fp16 dinv-prescaled h2
__device__ int g_cnt [NN];
__device__ int g_off [NN + 1];
__device__ int g_fill[NN];
__device__ int g_csr_src[EMAX];
__device__ int g_bsum[NB];
__device__ int g_boff[NB];
__device__ int g_is64;

__device__ __forceinline__ uint32_t f2tf32(float f) {
    uint32_t u; asm("cvt.rna.tf32.f32 %0, %1;" : "=r"(u) : "f"(f)); return u;
}
__device__ __forceinline__ void mma_tf32(float4& c, uint32_t a0, uint32_t a1,
                                         uint32_t a2, uint32_t a3,
                                         uint32_t b0, uint32_t b1) {
    asm volatile("mma.sync.aligned.m16n8k8.row.col.f32.tf32.tf32.f32 "
                 "{%0,%1,%2,%3}, {%4,%5,%6,%7}, {%8,%9}, {%0,%1,%2,%3};"
                 : "+f"(c.x), "+f"(c.y), "+f"(c.z), "+f"(c.w)
                 : "r"(a0), "r"(a1), "r"(a2), "r"(a3), "r"(b0), "r"(b1));
}

// ---------------- detect edge width + zero counts (fused) ----------------
__global__ void k_init(const int* __restrict__ ei32) {
    int i = blockIdx.x * blockDim.x + threadIdx.x;
    if (i < NN) g_cnt[i] = 0;
    if (blockIdx.x == 0 && threadIdx.x == 0) {
        int zeros = 0;
        #pragma unroll
        for (int j = 1; j < 128; j += 2) zeros += (ei32[j] == 0);
        g_is64 = (zeros >= 48) ? 1 : 0;
    }
}

__device__ __forceinline__ void load_edge(const void* ei, int e, int E, int& s, int& d) {
    if (g_is64) {
        const long long* p = (const long long*)ei;
        s = (int)p[e]; d = (int)p[E + e];
    } else {
        const int* p = (const int*)ei;
        s = p[e]; d = p[E + e];
    }
}

__global__ void k_count(const void* __restrict__ ei, int E) {
    int e = blockIdx.x * blockDim.x + threadIdx.x;
    if (e < E) {
        int s, d; load_edge(ei, e, E, s, d);
        if ((unsigned)d < NN) atomicAdd(&g_cnt[d], 1);
    }
}

// ---------------- chip-wide 3-phase exclusive scan ----------------
__global__ void k_bsum() {
    int i = blockIdx.x * 256 + threadIdx.x;
    int c = (i < NN) ? g_cnt[i] : 0;
    #pragma unroll
    for (int o = 16; o; o >>= 1) c += __shfl_down_sync(0xffffffffu, c, o);
    __shared__ int ws[8];
    if ((threadIdx.x & 31) == 0) ws[threadIdx.x >> 5] = c;
    __syncthreads();
    if (threadIdx.x < 8) {
        int v = ws[threadIdx.x];
        #pragma unroll
        for (int o = 4; o; o >>= 1) v += __shfl_down_sync(0xffu, v, o);
        if (threadIdx.x == 0) g_bsum[blockIdx.x] = v;
    }
}

__global__ void k_bscan() {
    __shared__ int sh[256];
    int t = threadIdx.x;
    int v = (t < NB) ? g_bsum[t] : 0;
    sh[t] = v;
    __syncthreads();
    for (int d = 1; d < 256; d <<= 1) {
        int u = (t >= d) ? sh[t - d] : 0;
        __syncthreads();
        sh[t] += u;
        __syncthreads();
    }
    if (t < NB) g_boff[t] = sh[t] - v;
    if (t == NB - 1) g_off[NN] = sh[t];
}

__global__ void k_offsets() {
    int i    = blockIdx.x * 256 + threadIdx.x;
    int c    = (i < NN) ? g_cnt[i] : 0;
    int lane = threadIdx.x & 31, w = threadIdx.x >> 5;
    int inc  = c;
    #pragma unroll
    for (int o = 1; o < 32; o <<= 1) {
        int u = __shfl_up_sync(0xffffffffu, inc, o);
        if (lane >= o) inc += u;
    }
    __shared__ int ws[8];
    if (lane == 31) ws[w] = inc;
    __syncthreads();
    if (threadIdx.x == 0) {
        int r = 0;
        #pragma unroll
        for (int j = 0; j < 8; j++) { int t = ws[j]; ws[j] = r; r += t; }
    }
    __syncthreads();
    int excl = inc - c + ws[w] + g_boff[blockIdx.x];
    if (i < NN) {
        g_off[i]  = excl;
        g_fill[i] = excl;
        g_dinv[i] = rsqrtf((float)c + 1.0f);
    }
}

__global__ void k_fill(const void* __restrict__ ei, int E) {
    int e = blockIdx.x * blockDim.x + threadIdx.x;
    if (e < E) {
        int s, d; load_edge(ei, e, E, s, d);
        if ((unsigned)s < NN && (unsigned)d < NN) {
            int pos = atomicAdd(&g_fill[d], 1);
            if (pos < EMAX) g_csr_src[pos] = s;
        }
    }
}

// ---------------- tensor-core GEMM (tf32) + dinv prescale -> fp16 ----------------
// Block: 64 rows x N cols, 256 threads = 8 warps (4 row x 2 col).
template<int N, int LAYER>
__global__ void k_gemm_tc(const float* __restrict__ Xin, const float* __restrict__ W) {
    constexpr int K    = 128;
    constexpr int ROWS = 64;
    constexpr int XS   = 132;       // sX row stride (words)
    constexpr int WS   = N + 8;     // sW row stride
    constexpr int NW   = N / 2;     // warp n-extent
    constexpr int NT   = NW / 8;    // n8 tiles per warp
    extern __shared__ uint32_t smem[];
    uint32_t* sX = smem;                 // ROWS x XS
    uint32_t* sW = smem + ROWS * XS;     // K x WS

    const float* X  = (LAYER == 1) ? Xin : g_h1r;
    uint32_t*    hs = (LAYER == 1) ? (uint32_t*)g_hs1h : (uint32_t*)g_hs2h;

    const int tid  = threadIdx.x;
    const int row0 = blockIdx.x * ROWS;

    const float4* xg = (const float4*)(X + (size_t)row0 * K);
    #pragma unroll
    for (int j = tid; j < ROWS * K / 4; j += 256) {
        float4 v = xg[j];
        uint32_t* p = sX + (j >> 5) * XS + ((j & 31) << 2);
        p[0] = f2tf32(v.x); p[1] = f2tf32(v.y); p[2] = f2tf32(v.z); p[3] = f2tf32(v.w);
    }
    const float4* wg = (const float4*)W;
    #pragma unroll
    for (int j = tid; j < K * N / 4; j += 256) {
        float4 v = wg[j];
        uint32_t* p = sW + (j / (N / 4)) * WS + ((j % (N / 4)) << 2);
        p[0] = f2tf32(v.x); p[1] = f2tf32(v.y); p[2] = f2tf32(v.z); p[3] = f2tf32(v.w);
    }
    __syncthreads();

    const int warp = tid >> 5, lane = tid & 31;
    const int wr   = (warp & 3) * 16;
    const int wn   = (warp >> 2) * NW;
    const int grp  = lane >> 2, tig = lane & 3;

    float4 acc[NT];
    #pragma unroll
    for (int t = 0; t < NT; t++) acc[t] = make_float4(0.f, 0.f, 0.f, 0.f);

    #pragma unroll
    for (int k8 = 0; k8 < K / 8; k8++) {
        const uint32_t* ax = sX + (wr + grp) * XS + k8 * 8 + tig;
        uint32_t a0 = ax[0];
        uint32_t a1 = ax[8 * XS];
        uint32_t a2 = ax[4];
        uint32_t a3 = ax[8 * XS + 4];
        const uint32_t* bx = sW + (k8 * 8 + tig) * WS + wn + grp;
        #pragma unroll
        for (int t = 0; t < NT; t++) {
            uint32_t b0 = bx[t * 8];
            uint32_t b1 = bx[t * 8 + 4 * WS];
            mma_tf32(acc[t], a0, a1, a2, a3, b0, b1);
        }
    }

    // epilogue: scale by dinv(row), pack adjacent pair to half2, store 4B
    const int r0 = row0 + wr + grp;
    const int r1 = r0 + 8;
    const float d0 = g_dinv[r0], d1 = g_dinv[r1];
    #pragma unroll
    for (int t = 0; t < NT; t++) {
        int c = wn + t * 8 + 2 * tig;
        __half2 h0 = __floats2half2_rn(acc[t].x * d0, acc[t].y * d0);
        __half2 h1 = __floats2half2_rn(acc[t].z * d1, acc[t].w * d1);
        hs[((size_t)r0 * N + c) >> 1] = *(uint32_t*)&h0;
        hs[((size_t)r1 * N + c) >> 1] = *(uint32_t*)&h1;
    }
}

// ---------------- pull aggregation (fp16 gather, fp32 accumulate) ----------------
__device__ __forceinline__ void hacc4(float4& a, uint2 u) {
    float2 lo = __half22float2(*(__half2*)&u.x);
    float2 hi = __half22float2(*(__half2*)&u.y);
    a.x += lo.x; a.y += lo.y; a.z += hi.x; a.w += hi.y;
}
__device__ __forceinline__ void hacc2(float2& a, uint32_t u) {
    float2 v = __half22float2(*(__half2*)&u);
    a.x += v.x; a.y += v.y;
}

__global__ void k_aggr1(const float* __restrict__ b1) {
    int node = blockIdx.x * 8 + (threadIdx.x >> 5);
    if (node >= NN) return;
    int lane = threadIdx.x & 31;
    const uint2* hs = (const uint2*)g_hs1h;   // 32 uint2 (4 halves each) per node

    float4 a0, a1, a2, a3;
    a0 = make_float4(0.f, 0.f, 0.f, 0.f);
    hacc4(a0, hs[node * 32 + lane]);          // self term
    a1 = a2 = a3 = make_float4(0.f, 0.f, 0.f, 0.f);

    int off0 = g_off[node], off1 = g_off[node + 1];
    for (int base = off0; base < off1; base += 32) {
        int idx = base + lane;
        int s   = (idx < off1) ? __ldg(&g_csr_src[idx]) : 0;
        int m   = min(32, off1 - base);
        int k   = 0;
        for (; k + 4 <= m; k += 4) {
            int s0 = __shfl_sync(0xffffffffu, s, k);
            int s1 = __shfl_sync(0xffffffffu, s, k + 1);
            int s2 = __shfl_sync(0xffffffffu, s, k + 2);
            int s3 = __shfl_sync(0xffffffffu, s, k + 3);
            uint2 v0 = hs[s0 * 32 + lane];
            uint2 v1 = hs[s1 * 32 + lane];
            uint2 v2 = hs[s2 * 32 + lane];
            uint2 v3 = hs[s3 * 32 + lane];
            hacc4(a0, v0); hacc4(a1, v1); hacc4(a2, v2); hacc4(a3, v3);
        }
        for (; k < m; k++) {
            int sk = __shfl_sync(0xffffffffu, s, k);
            hacc4(a0, hs[sk * 32 + lane]);
        }
    }
    float d   = g_dinv[node];
    float4 bb = ((const float4*)b1)[lane];
    float4 r;
    r.x = fmaxf(0.0f, (a0.x + a1.x + a2.x + a3.x) * d + bb.x);
    r.y = fmaxf(0.0f, (a0.y + a1.y + a2.y + a3.y) * d + bb.y);
    r.z = fmaxf(0.0f, (a0.z + a1.z + a2.z + a3.z) * d + bb.z);
    r.w = fmaxf(0.0f, (a0.w + a1.w + a2.w + a3.w) * d + bb.w);
    ((float4*)g_h1r)[node * 32 + lane] = r;
}

__global__ void k_aggr2(const float* __restrict__ b2, float* __restrict__ out) {
    int node = blockIdx.x * 8 + (threadIdx.x >> 5);
    if (node >= NN) return;
    int lane = threadIdx.x & 31;
    const uint32_t* hs = (const uint32_t*)g_hs2h;   // 32 half2 words per node

    float2 a0, a1, a2, a3;
    a0 = make_float2(0.f, 0.f);
    hacc2(a0, hs[node * 32 + lane]);                // self term
    a1 = a2 = a3 = make_float2(0.f, 0.f);

    int off0 = g_off[node], off1 = g_off[node + 1];
    for (int base = off0; base < off1; base += 32) {
        int idx = base + lane;
        int s   = (idx < off1) ? __ldg(&g_csr_src[idx]) : 0;
        int m   = min(32, off1 - base);
        int k   = 0;
        for (; k + 4 <= m; k += 4) {
            int s0 = __shfl_sync(0xffffffffu, s, k);
            int s1 = __shfl_sync(0xffffffffu, s, k + 1);
            int s2 = __shfl_sync(0xffffffffu, s, k + 2);
            int s3 = __shfl_sync(0xffffffffu, s, k + 3);
            uint32_t v0 = hs[s0 * 32 + lane];
            uint32_t v1 = hs[s1 * 32 + lane];
            uint32_t v2 = hs[s2 * 32 + lane];
            uint32_t v3 = hs[s3 * 32 + lane];
            hacc2(a0, v0); hacc2(a1, v1); hacc2(a2, v2); hacc2(a3, v3);
        }
        for (; k < m; k++) {
            int sk = __shfl_sync(0xffffffffu, s, k);
            hacc2(a0, hs[sk * 32 + lane]);
        }
    }
    float d   = g_dinv[node];
    float2 bb = ((const float2*)b2)[lane];
    float2 r;
    r.x = (a0.x + a1.x + a2.x + a3.x) * d + bb.x;
    r.y = (a0.y + a1.y + a2.y + a3.y) * d + bb.y;
    ((float2*)out)[node * 32 + lane] = r;
}

// ---------------- launch ----------------
extern "C" void kernel_launch(void* const* d_in, const int* in_sizes, int n_in,
                              void* d_out, int out_size) {
    const float* x  = (const float*)d_in[0];
    const void*  ei = d_in[1];
    const float* W1 = (const float*)d_in[2];
    const float* b1 = (const float*)d_in[3];
    const float* W2 = (const float*)d_in[4];
    const float* b2 = (const float*)d_in[5];
    const int E = in_sizes[1] / 2;

    constexpr int SM1 = (64 * 132 + 128 * (DH   + 8)) * 4;
    constexpr int SM2 = (64 * 132 + 128 * (DOUT + 8)) * 4;
    cudaFuncSetAttribute(k_gemm_tc<DH, 1>,
                         cudaFuncAttributeMaxDynamicSharedMemorySize, SM1);
    cudaFuncSetAttribute(k_gemm_tc<DOUT, 2>,
                         cudaFuncAttributeMaxDynamicSharedMemorySize, SM2);

    k_init   <<<NB, 256>>>((const int*)ei);
    k_count  <<<(E + 255) / 256, 256>>>(ei, E);
    k_bsum   <<<NB, 256>>>();
    k_bscan  <<<1, 256>>>();
    k_offsets<<<NB, 256>>>();
    k_fill   <<<(E + 255) / 256, 256>>>(ei, E);

    // Layer 1
    k_gemm_tc<DH, 1><<<NN / 64, 256, SM1>>>(x, W1);
    k_aggr1<<<(NN + 7) / 8, 256>>>(b1);

    // Layer 2
    k_gemm_tc<DOUT, 2><<<NN / 64, 256, SM2>>>(nullptr, W2);
    k_aggr2<<<(NN + 7) / 8, 256>>>(b2, (float*)d_out);
}

// round 8
// speedup vs baseline: 3.6282x; 1.0925x over previous
#include <cuda_runtime.h>
#include <cuda_fp16.h>
#include <cstdint>

#define NN    40000
#define DH    128
#define DOUT  64
#define EMAX  700000
#define NB    157           // ceil(40000/256)

// ---------------- scratch (device globals; no allocation allowed) ----------------
__device__ __align__(16) float  g_dinv[NN];
__device__ __align__(16) __half g_hs1h[NN * DH];   // fp16 dinv-prescaled h1
__device__ __align__(16) float  g_h1r [NN * DH];   // relu(layer1 out), fp32
__device__ __align__(16) __half g_hs2h[NN * DOUT]; // fp16 dinv-prescaled h2
__device__ int g_cnt [NN];
__device__ int g_off [NN + 1];
__device__ int g_fill[NN];
__device__ int g_csr_src[EMAX];
__device__ int g_bsum[NB];
__device__ int g_is64;

__device__ __forceinline__ void mma_f16(float4& c, uint32_t a0, uint32_t a1,
                                        uint32_t a2, uint32_t a3,
                                        uint32_t b0, uint32_t b1) {
    asm volatile("mma.sync.aligned.m16n8k16.row.col.f32.f16.f16.f32 "
                 "{%0,%1,%2,%3}, {%4,%5,%6,%7}, {%8,%9}, {%0,%1,%2,%3};"
                 : "+f"(c.x), "+f"(c.y), "+f"(c.z), "+f"(c.w)
                 : "r"(a0), "r"(a1), "r"(a2), "r"(a3), "r"(b0), "r"(b1));
}

// ---------------- init: zero counts, detect edge width ----------------
__global__ void k_init(const int* __restrict__ ei32) {
    int i = blockIdx.x * blockDim.x + threadIdx.x;
    if (i < NN) g_cnt[i] = 0;
    if (i == 0) {
        int zeros = 0;
        #pragma unroll
        for (int j = 1; j < 128; j += 2) zeros += (ei32[j] == 0);
        g_is64 = (zeros >= 48) ? 1 : 0;
    }
}

__device__ __forceinline__ void load_edge(const void* ei, int e, int E, int& s, int& d) {
    if (g_is64) {
        const long long* p = (const long long*)ei;
        s = (int)p[e]; d = (int)p[E + e];
    } else {
        const int* p = (const int*)ei;
        s = p[e]; d = p[E + e];
    }
}

__global__ void k_count(const void* __restrict__ ei, int E) {
    int e = blockIdx.x * blockDim.x + threadIdx.x;
    if (e < E) {
        int s, d; load_edge(ei, e, E, s, d);
        if ((unsigned)d < NN) atomicAdd(&g_cnt[d], 1);
    }
}

// ---------------- scan phase 1: per-block sums ----------------
__global__ void k_bsum() {
    int i = blockIdx.x * 256 + threadIdx.x;
    int c = (i < NN) ? g_cnt[i] : 0;
    #pragma unroll
    for (int o = 16; o; o >>= 1) c += __shfl_down_sync(0xffffffffu, c, o);
    __shared__ int ws[8];
    if ((threadIdx.x & 31) == 0) ws[threadIdx.x >> 5] = c;
    __syncthreads();
    if (threadIdx.x < 8) {
        int v = ws[threadIdx.x];
        #pragma unroll
        for (int o = 4; o; o >>= 1) v += __shfl_down_sync(0xffu, v, o);
        if (threadIdx.x == 0) g_bsum[blockIdx.x] = v;
    }
}

// ---------------- scan phase 2: offsets (block prefix computed inline) ----------------
__global__ void k_offsets() {
    const int b = blockIdx.x;
    const int t = threadIdx.x;
    __shared__ int sred[8];
    __shared__ int ws[8];
    __shared__ int s_boff;

    // inclusive sum of g_bsum[0..b] across the block (NB=157 < 256)
    int vtot = (t < NB && t <= b) ? g_bsum[t] : 0;
    #pragma unroll
    for (int o = 16; o; o >>= 1) vtot += __shfl_down_sync(0xffffffffu, vtot, o);
    if ((t & 31) == 0) sred[t >> 5] = vtot;
    __syncthreads();
    if (t == 0) {
        int r = 0;
        #pragma unroll
        for (int j = 0; j < 8; j++) r += sred[j];
        s_boff = r - g_bsum[b];              // exclusive block offset
        if (b == NB - 1) g_off[NN] = r;      // total edge count
    }

    // per-element exclusive scan within the block
    int i    = b * 256 + t;
    int c    = (i < NN) ? g_cnt[i] : 0;
    int lane = t & 31, w = t >> 5;
    int inc  = c;
    #pragma unroll
    for (int o = 1; o < 32; o <<= 1) {
        int u = __shfl_up_sync(0xffffffffu, inc, o);
        if (lane >= o) inc += u;
    }
    __syncthreads();                 // sred reads done before ws writes (same smem phase)
    if (lane == 31) ws[w] = inc;
    __syncthreads();
    if (t == 0) {
        int r = 0;
        #pragma unroll
        for (int j = 0; j < 8; j++) { int q = ws[j]; ws[j] = r; r += q; }
    }
    __syncthreads();
    int excl = s_boff + ws[w] + (inc - c);
    if (i < NN) {
        g_off[i]  = excl;
        g_fill[i] = excl;
        g_dinv[i] = rsqrtf((float)c + 1.0f);
    }
}

__global__ void k_fill(const void* __restrict__ ei, int E) {
    int e = blockIdx.x * blockDim.x + threadIdx.x;
    if (e < E) {
        int s, d; load_edge(ei, e, E, s, d);
        if ((unsigned)s < NN && (unsigned)d < NN) {
            int pos = atomicAdd(&g_fill[d], 1);
            if (pos < EMAX) g_csr_src[pos] = s;
        }
    }
}

// ---------------- tensor-core GEMM (fp16 in, fp32 accum) + dinv prescale -> fp16 ----------------
// Block: 64 rows x N cols, 256 threads = 8 warps (4 row x 2 col). mma.m16n8k16.
// sX: [64][68] half2 words (K/2=64 used). sW: W transposed [N][68] half2 words.
// Stride 68 == 4 (mod 32) -> fragment loads conflict-free.
template<int N, int LAYER>
__global__ void k_gemm_h(const float* __restrict__ Xin, const float* __restrict__ W) {
    constexpr int K    = 128;
    constexpr int KW   = K / 2;     // 64 half2 words per row
    constexpr int ROWS = 64;
    constexpr int XSW  = 68;
    constexpr int WSW  = 68;
    constexpr int NW   = N / 2;
    constexpr int NT   = NW / 8;
    extern __shared__ uint32_t smem[];
    uint32_t* sX = smem;                  // ROWS x XSW
    uint32_t* sW = smem + ROWS * XSW;     // N x WSW

    const float* X  = (LAYER == 1) ? Xin : g_h1r;
    uint32_t*    hs = (LAYER == 1) ? (uint32_t*)g_hs1h : (uint32_t*)g_hs2h;

    const int tid  = threadIdx.x;
    const int row0 = blockIdx.x * ROWS;

    // stage X (row-major, fp32 -> half2 words)
    const float4* xg = (const float4*)(X + (size_t)row0 * K);
    #pragma unroll
    for (int j = tid; j < ROWS * K / 4; j += 256) {
        float4 v = xg[j];
        int r = j >> 5, wq = (j & 31) << 1;
        __half2 h0 = __floats2half2_rn(v.x, v.y);
        __half2 h1 = __floats2half2_rn(v.z, v.w);
        sX[r * XSW + wq]     = *(uint32_t*)&h0;
        sX[r * XSW + wq + 1] = *(uint32_t*)&h1;
    }
    // stage W transposed: sW[n][kp] = (W[2kp][n], W[2kp+1][n])
    #pragma unroll
    for (int j = tid; j < N * KW; j += 256) {
        int n = j % N, kp = j / N;
        __half2 h = __floats2half2_rn(W[(2 * kp) * N + n], W[(2 * kp + 1) * N + n]);
        sW[n * WSW + kp] = *(uint32_t*)&h;
    }
    __syncthreads();

    const int warp = tid >> 5, lane = tid & 31;
    const int wr   = (warp & 3) * 16;
    const int wn   = (warp >> 2) * NW;
    const int grp  = lane >> 2, tig = lane & 3;

    float4 acc[NT];
    #pragma unroll
    for (int t = 0; t < NT; t++) acc[t] = make_float4(0.f, 0.f, 0.f, 0.f);

    #pragma unroll
    for (int kb = 0; kb < K / 16; kb++) {
        const uint32_t* ax = sX + (wr + grp) * XSW + kb * 8 + tig;
        uint32_t a0 = ax[0];
        uint32_t a1 = ax[8 * XSW];
        uint32_t a2 = ax[4];
        uint32_t a3 = ax[8 * XSW + 4];
        const uint32_t* bx = sW + (wn + grp) * WSW + kb * 8 + tig;
        #pragma unroll
        for (int t = 0; t < NT; t++) {
            uint32_t b0 = bx[t * 8 * WSW];
            uint32_t b1 = bx[t * 8 * WSW + 4];
            mma_f16(acc[t], a0, a1, a2, a3, b0, b1);
        }
    }

    const int r0 = row0 + wr + grp;
    const int r1 = r0 + 8;
    const float d0 = g_dinv[r0], d1 = g_dinv[r1];
    #pragma unroll
    for (int t = 0; t < NT; t++) {
        int c = wn + t * 8 + 2 * tig;
        __half2 h0 = __floats2half2_rn(acc[t].x * d0, acc[t].y * d0);
        __half2 h1 = __floats2half2_rn(acc[t].z * d1, acc[t].w * d1);
        hs[((size_t)r0 * N + c) >> 1] = *(uint32_t*)&h0;
        hs[((size_t)r1 * N + c) >> 1] = *(uint32_t*)&h1;
    }
}

// ---------------- pull aggregation (fp16 gather, fp32 accumulate) ----------------
__device__ __forceinline__ void hacc4(float4& a, uint2 u) {
    float2 lo = __half22float2(*(__half2*)&u.x);
    float2 hi = __half22float2(*(__half2*)&u.y);
    a.x += lo.x; a.y += lo.y; a.z += hi.x; a.w += hi.y;
}
__device__ __forceinline__ void hacc2(float2& a, uint32_t u) {
    float2 v = __half22float2(*(__half2*)&u);
    a.x += v.x; a.y += v.y;
}

__global__ void k_aggr1(const float* __restrict__ b1) {
    int node = blockIdx.x * 8 + (threadIdx.x >> 5);
    if (node >= NN) return;
    int lane = threadIdx.x & 31;
    const uint2* hs = (const uint2*)g_hs1h;

    float4 a0, a1, a2, a3;
    a0 = make_float4(0.f, 0.f, 0.f, 0.f);
    hacc4(a0, hs[node * 32 + lane]);          // self term
    a1 = a2 = a3 = make_float4(0.f, 0.f, 0.f, 0.f);

    int off0 = g_off[node], off1 = g_off[node + 1];
    for (int base = off0; base < off1; base += 32) {
        int idx = base + lane;
        int s   = (idx < off1) ? __ldg(&g_csr_src[idx]) : 0;
        int m   = min(32, off1 - base);
        int k   = 0;
        for (; k + 4 <= m; k += 4) {
            int s0 = __shfl_sync(0xffffffffu, s, k);
            int s1 = __shfl_sync(0xffffffffu, s, k + 1);
            int s2 = __shfl_sync(0xffffffffu, s, k + 2);
            int s3 = __shfl_sync(0xffffffffu, s, k + 3);
            uint2 v0 = hs[s0 * 32 + lane];
            uint2 v1 = hs[s1 * 32 + lane];
            uint2 v2 = hs[s2 * 32 + lane];
            uint2 v3 = hs[s3 * 32 + lane];
            hacc4(a0, v0); hacc4(a1, v1); hacc4(a2, v2); hacc4(a3, v3);
        }
        for (; k < m; k++) {
            int sk = __shfl_sync(0xffffffffu, s, k);
            hacc4(a0, hs[sk * 32 + lane]);
        }
    }
    float d   = g_dinv[node];
    float4 bb = ((const float4*)b1)[lane];
    float4 r;
    r.x = fmaxf(0.0f, (a0.x + a1.x + a2.x + a3.x) * d + bb.x);
    r.y = fmaxf(0.0f, (a0.y + a1.y + a2.y + a3.y) * d + bb.y);
    r.z = fmaxf(0.0f, (a0.z + a1.z + a2.z + a3.z) * d + bb.z);
    r.w = fmaxf(0.0f, (a0.w + a1.w + a2.w + a3.w) * d + bb.w);
    ((float4*)g_h1r)[node * 32 + lane] = r;
}

__global__ void k_aggr2(const float* __restrict__ b2, float* __restrict__ out) {
    int node = blockIdx.x * 8 + (threadIdx.x >> 5);
    if (node >= NN) return;
    int lane = threadIdx.x & 31;
    const uint32_t* hs = (const uint32_t*)g_hs2h;

    float2 a0, a1, a2, a3;
    a0 = make_float2(0.f, 0.f);
    hacc2(a0, hs[node * 32 + lane]);                // self term
    a1 = a2 = a3 = make_float2(0.f, 0.f);

    int off0 = g_off[node], off1 = g_off[node + 1];
    for (int base = off0; base < off1; base += 32) {
        int idx = base + lane;
        int s   = (idx < off1) ? __ldg(&g_csr_src[idx]) : 0;
        int m   = min(32, off1 - base);
        int k   = 0;
        for (; k + 4 <= m; k += 4) {
            int s0 = __shfl_sync(0xffffffffu, s, k);
            int s1 = __shfl_sync(0xffffffffu, s, k + 1);
            int s2 = __shfl_sync(0xffffffffu, s, k + 2);
            int s3 = __shfl_sync(0xffffffffu, s, k + 3);
            uint32_t v0 = hs[s0 * 32 + lane];
            uint32_t v1 = hs[s1 * 32 + lane];
            uint32_t v2 = hs[s2 * 32 + lane];
            uint32_t v3 = hs[s3 * 32 + lane];
            hacc2(a0, v0); hacc2(a1, v1); hacc2(a2, v2); hacc2(a3, v3);
        }
        for (; k < m; k++) {
            int sk = __shfl_sync(0xffffffffu, s, k);
            hacc2(a0, hs[sk * 32 + lane]);
        }
    }
    float d   = g_dinv[node];
    float2 bb = ((const float2*)b2)[lane];
    float2 r;
    r.x = (a0.x + a1.x + a2.x + a3.x) * d + bb.x;
    r.y = (a0.y + a1.y + a2.y + a3.y) * d + bb.y;
    ((float2*)out)[node * 32 + lane] = r;
}

// ---------------- launch ----------------
extern "C" void kernel_launch(void* const* d_in, const int* in_sizes, int n_in,
                              void* d_out, int out_size) {
    const float* x  = (const float*)d_in[0];
    const void*  ei = d_in[1];
    const float* W1 = (const float*)d_in[2];
    const float* b1 = (const float*)d_in[3];
    const float* W2 = (const float*)d_in[4];
    const float* b2 = (const float*)d_in[5];
    const int E = in_sizes[1] / 2;

    constexpr int SM1 = (64 * 68 + DH   * 68) * 4;   // 52224 B
    constexpr int SM2 = (64 * 68 + DOUT * 68) * 4;   // 34816 B
    cudaFuncSetAttribute(k_gemm_h<DH, 1>,
                         cudaFuncAttributeMaxDynamicSharedMemorySize, SM1);
    cudaFuncSetAttribute(k_gemm_h<DOUT, 2>,
                         cudaFuncAttributeMaxDynamicSharedMemorySize, SM2);

    k_init   <<<NB, 256>>>((const int*)ei);
    k_count  <<<(E + 255) / 256, 256>>>(ei, E);
    k_bsum   <<<NB, 256>>>();
    k_offsets<<<NB, 256>>>();
    k_fill   <<<(E + 255) / 256, 256>>>(ei, E);

    // Layer 1
    k_gemm_h<DH, 1><<<NN / 64, 256, SM1>>>(x, W1);
    k_aggr1<<<(NN + 7) / 8, 256>>>(b1);

    // Layer 2
    k_gemm_h<DOUT, 2><<<NN / 64, 256, SM2>>>(nullptr, W2);
    k_aggr2<<<(NN + 7) / 8, 256>>>(b2, (float*)d_out);
}